// round 8
// baseline (speedup 1.0000x reference)
#include <cuda_runtime.h>
#include <cuda_bf16.h>
#include <cstdint>

// LogSignature depth=4 of path (B=128, T=512, C=8).
// Output per batch: [L1(8) | L2(64) | L3(512) | L4(4096)] = 4680 floats.
//
// ROUND 8 (re-bench of R7; infra failure): R6 cluster structure + in-place
// f32x2 asm. R6 showed ~47 issued instr/iter vs 29 hand-counted: ptxas MOV
// pairs around out-of-place inline-asm results. All loop-carried accumulators
// now use "+l" read-modify-write asm (FFMA R,a,b,R), and the dx pointer walks
// instead of t*CH indexing.

#define BATCH 128
#define TLEN  512
#define CH    8
#define NSTEP (TLEN - 1)      // 511
#define NQ    128             // steps per quarter (packed loop length)
#define OUT_STRIDE 4680
#define OFF_L2 8
#define OFF_L3 72
#define OFF_L4 584

typedef unsigned long long u64;

// fresh-output forms (inputs preserved, output is a new temp)
__device__ __forceinline__ u64 ffma2(u64 a, u64 b, u64 c) {
    u64 d; asm("fma.rn.f32x2 %0, %1, %2, %3;" : "=l"(d) : "l"(a), "l"(b), "l"(c)); return d;
}
__device__ __forceinline__ u64 fmul2(u64 a, u64 b) {
    u64 d; asm("mul.rn.f32x2 %0, %1, %2;" : "=l"(d) : "l"(a), "l"(b)); return d;
}
// in-place accumulate forms: acc = a*b + acc / acc += a  (no result MOVs)
#define FFMA2_ACC(acc, a, b) \
    asm("fma.rn.f32x2 %0, %1, %2, %0;" : "+l"(acc) : "l"(a), "l"(b))
#define FADD2_ACC(acc, a) \
    asm("add.rn.f32x2 %0, %0, %1;" : "+l"(acc) : "l"(a))

__device__ __forceinline__ u64 pack2(float x, float y) {
    u64 d; asm("mov.b64 %0, {%1, %2};" : "=l"(d) : "f"(x), "f"(y)); return d;
}
__device__ __forceinline__ void unpack2(u64 a, float& x, float& y) {
    asm("mov.b64 {%0, %1}, %2;" : "=f"(x), "=f"(y) : "l"(a));
}
__device__ __forceinline__ uint32_t smem_u32(const void* p) {
    uint32_t a;
    asm("{ .reg .u64 t; cvta.to.shared.u64 t, %1; cvt.u32.u64 %0, t; }" : "=r"(a) : "l"(p));
    return a;
}
__device__ __forceinline__ uint32_t mapa_rank(uint32_t addr, uint32_t rank) {
    uint32_t r; asm("mapa.shared::cluster.u32 %0, %1, %2;" : "=r"(r) : "r"(addr), "r"(rank));
    return r;
}
__device__ __forceinline__ float4 ld_dsmem_v4(uint32_t addr) {
    float4 v;
    asm volatile("ld.shared::cluster.v4.f32 {%0,%1,%2,%3}, [%4];"
                 : "=f"(v.x), "=f"(v.y), "=f"(v.z), "=f"(v.w) : "r"(addr));
    return v;
}
__device__ __forceinline__ void cluster_sync_() {
    asm volatile("barrier.cluster.arrive.aligned;" ::: "memory");
    asm volatile("barrier.cluster.wait.aligned;" ::: "memory");
}

// packed constants (both lanes): 0.5f, 1/6f, 1/24f
#define C2P 0x3F0000003F000000ULL
#define C3P 0x3E2AAAAB3E2AAAABULL
#define C4P 0x3D2AAAAB3D2AAAABULL

__global__ void __launch_bounds__(512, 2) __cluster_dims__(2, 1, 1)
logsig_fused(const float* __restrict__ path, float* __restrict__ out)
{
    __shared__ __align__(16) u64 s_dx2[NQ * CH];          // 8 KB
    __shared__ float sB1[8], sB2[64], sB3[512];           // lane-B levels (intra-CTA)
    __shared__ __align__(16) float sH[584];               // own half levels 1..3
    __shared__ __align__(16) float sH4[4096];             // own half L4 (16 KB)
    __shared__ __align__(16) float sP[584];               // peer half levels 1..3
    __shared__ float sc[584];                             // combined levels 1..3

    const int b    = blockIdx.x >> 1;
    const int rank = blockIdx.x & 1;                      // cluster CTA rank
    const int tid  = threadIdx.x;
    const float* p = path + (size_t)b * TLEN * CH;

    const int baseA = (2 * rank) * NQ * CH;
    const int baseB = (2 * rank + 1) * NQ * CH;

    // Build interleaved increments: s_dx2[t*8+c] = (dx quarter 2r, dx quarter 2r+1)
    for (int idx = tid; idx < NQ * CH; idx += 512) {
        const float dxA = p[baseA + idx + CH] - p[baseA + idx];
        float dxB = 0.0f;
        if (baseB + idx < NSTEP * CH)      // only global step 511 is padding
            dxB = p[baseB + idx + CH] - p[baseB + idx];
        s_dx2[idx] = pack2(dxA, dxB);
    }
    __syncthreads();

    const int i = tid >> 6;
    const int j = (tid >> 3) & 7;
    const int k = tid & 7;

    u64 r1 = 0, r2 = 0, r3 = 0;
    u64 a0 = 0, a1 = 0, a2 = 0, a3 = 0, a4 = 0, a5 = 0, a6 = 0, a7 = 0;

    const u64 c2 = C2P, c3 = C3P, c4 = C4P;

    const u64* d = s_dx2;
    #pragma unroll 1
    for (int t = 0; t < NQ; ++t, d += CH) {
        const ulonglong2 q0 = *(const ulonglong2*)(d + 0);
        const ulonglong2 q1 = *(const ulonglong2*)(d + 2);
        const ulonglong2 q2 = *(const ulonglong2*)(d + 4);
        const ulonglong2 q3 = *(const ulonglong2*)(d + 6);
        const u64 di = d[i];
        const u64 dj = d[j];
        const u64 dk = d[k];

        const u64 djk  = fmul2(dj, dk);
        const u64 dijk = fmul2(di, djk);
        const u64 u = fmul2(r2, dk);     // OLD r2
        const u64 v = fmul2(r1, djk);    // OLD r1

        // level-4 rank-1 update (g fresh, then in-place accumulates)
        u64 g = ffma2(c2, u, r3);
        FFMA2_ACC(g, c3, v);
        FFMA2_ACC(g, c4, dijk);
        FFMA2_ACC(a0, g, q0.x);
        FFMA2_ACC(a1, g, q0.y);
        FFMA2_ACC(a2, g, q1.x);
        FFMA2_ACC(a3, g, q1.y);
        FFMA2_ACC(a4, g, q2.x);
        FFMA2_ACC(a5, g, q2.y);
        FFMA2_ACC(a6, g, q3.x);
        FFMA2_ACC(a7, g, q3.y);

        // level-3 (in place, uses OLD-r2/r1 via u, v)
        FADD2_ACC(r3, u);
        FFMA2_ACC(r3, c2, v);
        FFMA2_ACC(r3, c3, dijk);

        // level-2: r2 += dj * (r1 + 0.5*di)  (in place)
        const u64 tmp = ffma2(c2, di, r1);
        FFMA2_ACC(r2, dj, tmp);

        // level-1
        FADD2_ACC(r1, di);
    }

    // ---- unpack lanes: A = quarter 2r, B = quarter 2r+1 ----
    float A1, B1, A2, B2, A3, B3;
    unpack2(r1, A1, B1);
    unpack2(r2, A2, B2);
    unpack2(r3, A3, B3);
    float aA[8], aB[8];
    unpack2(a0, aA[0], aB[0]); unpack2(a1, aA[1], aB[1]);
    unpack2(a2, aA[2], aB[2]); unpack2(a3, aA[3], aB[3]);
    unpack2(a4, aA[4], aB[4]); unpack2(a5, aA[5], aB[5]);
    unpack2(a6, aA[6], aB[6]); unpack2(a7, aA[7], aB[7]);

    sB3[tid] = B3;
    if (k == 0)          sB2[i * 8 + j] = B2;
    if ((tid & 63) == 0) sB1[i] = B1;
    __syncthreads();

    // ---- Chen combine lanes -> this CTA's half-signature H_r ----
    const float h1v = A1 + B1;
    const float h2v = A2 + B2 + A1 * sB1[j];
    const float h3v = A3 + B3 + A1 * sB2[j * 8 + k] + A2 * sB1[k];

    float w[8];
    {
        const float* b3row = &sB3[(j * 8 + k) * 8];
        const float* b2row = &sB2[k * 8];
        #pragma unroll
        for (int l = 0; l < 8; ++l) {
            float t4 = aA[l] + aB[l];
            t4 = fmaf(A3, sB1[l], t4);
            t4 = fmaf(A2, b2row[l], t4);
            t4 = fmaf(A1, b3row[l], t4);
            w[l] = t4;
        }
    }

    // ---- publish own half in SMEM ----
    sH[72 + tid] = h3v;
    if (k == 0)          sH[8 + (tid >> 3)] = h2v;
    if ((tid & 63) == 0) sH[i] = h1v;
    {
        float4 w0 = {w[0], w[1], w[2], w[3]};
        float4 w1 = {w[4], w[5], w[6], w[7]};
        *(float4*)(&sH4[tid * 8])     = w0;
        *(float4*)(&sH4[tid * 8 + 4]) = w1;
    }

    // barrier.cluster orders the SMEM writes before peer DSMEM reads
    cluster_sync_();

    // ---- fetch peer half via DSMEM ----
    const uint32_t peer = (uint32_t)(rank ^ 1);
    {
        const uint32_t peerH = mapa_rank(smem_u32(sH), peer);
        for (int idx = tid; idx < 146; idx += 512)           // 584 floats = 146 float4
            *(float4*)(&sP[idx * 4]) = ld_dsmem_v4(peerH + idx * 16);
    }
    // peer L4 slice for this CTA's output columns l in [4*rank, 4*rank+4)
    float4 p4;
    {
        const uint32_t peer4 = mapa_rank(smem_u32(sH4), peer);
        p4 = ld_dsmem_v4(peer4 + (tid * 8 + 4 * rank) * 4);
    }
    __syncthreads();

    // ---- Chen combine: S = H0 (x) H1 (A-side = rank0 half, B-side = rank1 half) ----
    const float* Alev = (rank == 0) ? sH : sP;
    const float* Blev = (rank == 0) ? sP : sH;

    const float cA1 = Alev[i];
    const float cA2 = Alev[8 + (tid >> 3)];
    const float cA3 = Alev[72 + tid];

    const float c1v = cA1 + Blev[i];
    const float c2v = cA2 + Blev[8 + (tid >> 3)] + cA1 * Blev[j];
    const float c3v = cA3 + Blev[72 + tid] + cA1 * Blev[8 + j * 8 + k] + cA2 * Blev[k];

    // L4 combine for this CTA's 4 columns (l = 4*rank + m)
    float w4[4];
    {
        const float pv[4] = {p4.x, p4.y, p4.z, p4.w};
        #pragma unroll
        for (int m = 0; m < 4; ++m) {
            const int l = 4 * rank + m;
            const float A4v = (rank == 0) ? w[m] : pv[m];
            const float B4v = (rank == 0) ? pv[m] : w[4 + m];
            float t4 = A4v + B4v;
            t4 = fmaf(cA3, Blev[l], t4);
            t4 = fmaf(cA2, Blev[8 + k * 8 + l], t4);
            t4 = fmaf(cA1, Blev[72 + (j * 8 + k) * 8 + l], t4);
            w4[m] = t4;
        }
    }

    // publish combined levels for the log tail (CTA-local)
    sc[72 + tid] = c3v;
    if (k == 0)          sc[8 + (tid >> 3)] = c2v;
    if ((tid & 63) == 0) sc[i] = c1v;
    __syncthreads();

    // ---- closed-form log(1+x) truncated at depth 4 ----
    const float si = sc[i];
    const float sj = sc[j];
    const float sk = sc[k];
    const float s2ij  = c2v;
    const float s2jk  = sc[8 + j * 8 + k];
    const float s3ijk = c3v;

    const float cross = fmaf(si, s2jk, s2ij * sk);
    const float sss   = si * sj * sk;

    const float P = fmaf(1.0f / 3.0f, cross, -0.5f * s3ijk) - 0.25f * sss;
    const float Q = fmaf(1.0f / 3.0f, si * sj, -0.5f * s2ij);
    const float R = -0.5f * si;

    float* ob = out + (size_t)b * OUT_STRIDE;

    {
        float4 o;
        float ov[4];
        #pragma unroll
        for (int m = 0; m < 4; ++m) {
            const int l = 4 * rank + m;
            ov[m] = w4[m] + P * sc[l] + Q * sc[8 + k * 8 + l] + R * sc[72 + (j * 8 + k) * 8 + l];
        }
        o.x = ov[0]; o.y = ov[1]; o.z = ov[2]; o.w = ov[3];
        *(float4*)(&ob[OFF_L4 + tid * 8 + 4 * rank]) = o;
    }

    if (rank == 0) {
        ob[OFF_L3 + tid] = fmaf(1.0f / 3.0f, sss, fmaf(-0.5f, cross, s3ijk));
        if (k == 0)
            ob[OFF_L2 + i * 8 + j] = fmaf(-0.5f * si, sj, c2v);
        if ((tid & 63) == 0)
            ob[i] = c1v;
    }

    // keep peer SMEM alive until both CTAs are done
    cluster_sync_();
}

extern "C" void kernel_launch(void* const* d_in, const int* in_sizes, int n_in,
                              void* d_out, int out_size)
{
    const float* path = (const float*)d_in[0];
    float* out = (float*)d_out;
    logsig_fused<<<2 * BATCH, 512>>>(path, out);
}

// round 9
// speedup vs baseline: 1.0222x; 1.0222x over previous
#include <cuda_runtime.h>
#include <cuda_bf16.h>
#include <cstdint>

// LogSignature depth=4 of path (B=128, T=512, C=8).
// ROUND 9: R8 cluster kernel + software-pipelined prefetch of the
// critical-path d-values (di,dj,dk) one iteration ahead, manual unroll 2.
// FFMA2 costs 2 issue slots (measured); the remaining lever is stall removal.

#define BATCH 128
#define TLEN  512
#define CH    8
#define NSTEP (TLEN - 1)      // 511
#define NQ    128             // steps per quarter (packed loop length)
#define OUT_STRIDE 4680
#define OFF_L2 8
#define OFF_L3 72
#define OFF_L4 584

typedef unsigned long long u64;

__device__ __forceinline__ u64 ffma2(u64 a, u64 b, u64 c) {
    u64 d; asm("fma.rn.f32x2 %0, %1, %2, %3;" : "=l"(d) : "l"(a), "l"(b), "l"(c)); return d;
}
__device__ __forceinline__ u64 fmul2(u64 a, u64 b) {
    u64 d; asm("mul.rn.f32x2 %0, %1, %2;" : "=l"(d) : "l"(a), "l"(b)); return d;
}
#define FFMA2_ACC(acc, a, b) \
    asm("fma.rn.f32x2 %0, %1, %2, %0;" : "+l"(acc) : "l"(a), "l"(b))
#define FADD2_ACC(acc, a) \
    asm("add.rn.f32x2 %0, %0, %1;" : "+l"(acc) : "l"(a))

__device__ __forceinline__ u64 pack2(float x, float y) {
    u64 d; asm("mov.b64 %0, {%1, %2};" : "=l"(d) : "f"(x), "f"(y)); return d;
}
__device__ __forceinline__ void unpack2(u64 a, float& x, float& y) {
    asm("mov.b64 {%0, %1}, %2;" : "=f"(x), "=f"(y) : "l"(a));
}
__device__ __forceinline__ uint32_t smem_u32(const void* p) {
    uint32_t a;
    asm("{ .reg .u64 t; cvta.to.shared.u64 t, %1; cvt.u32.u64 %0, t; }" : "=r"(a) : "l"(p));
    return a;
}
__device__ __forceinline__ uint32_t mapa_rank(uint32_t addr, uint32_t rank) {
    uint32_t r; asm("mapa.shared::cluster.u32 %0, %1, %2;" : "=r"(r) : "r"(addr), "r"(rank));
    return r;
}
__device__ __forceinline__ float4 ld_dsmem_v4(uint32_t addr) {
    float4 v;
    asm volatile("ld.shared::cluster.v4.f32 {%0,%1,%2,%3}, [%4];"
                 : "=f"(v.x), "=f"(v.y), "=f"(v.z), "=f"(v.w) : "r"(addr));
    return v;
}
__device__ __forceinline__ void cluster_sync_() {
    asm volatile("barrier.cluster.arrive.aligned;" ::: "memory");
    asm volatile("barrier.cluster.wait.aligned;" ::: "memory");
}

// packed constants (both lanes): 0.5f, 1/6f, 1/24f
#define C2P 0x3F0000003F000000ULL
#define C3P 0x3E2AAAAB3E2AAAABULL
#define C4P 0x3D2AAAAB3D2AAAABULL

__global__ void __launch_bounds__(512, 2) __cluster_dims__(2, 1, 1)
logsig_fused(const float* __restrict__ path, float* __restrict__ out)
{
    __shared__ __align__(16) u64 s_dx2[NQ * CH];          // 8 KB
    __shared__ float sB1[8], sB2[64], sB3[512];           // lane-B levels (intra-CTA)
    __shared__ __align__(16) float sH[584];               // own half levels 1..3
    __shared__ __align__(16) float sH4[4096];             // own half L4 (16 KB)
    __shared__ __align__(16) float sP[584];               // peer half levels 1..3
    __shared__ float sc[584];                             // combined levels 1..3

    const int b    = blockIdx.x >> 1;
    const int rank = blockIdx.x & 1;                      // cluster CTA rank
    const int tid  = threadIdx.x;
    const float* p = path + (size_t)b * TLEN * CH;

    const int baseA = (2 * rank) * NQ * CH;
    const int baseB = (2 * rank + 1) * NQ * CH;

    // Build interleaved increments: s_dx2[t*8+c] = (dx quarter 2r, dx quarter 2r+1)
    for (int idx = tid; idx < NQ * CH; idx += 512) {
        const float dxA = p[baseA + idx + CH] - p[baseA + idx];
        float dxB = 0.0f;
        if (baseB + idx < NSTEP * CH)      // only global step 511 is padding
            dxB = p[baseB + idx + CH] - p[baseB + idx];
        s_dx2[idx] = pack2(dxA, dxB);
    }
    __syncthreads();

    const int i = tid >> 6;
    const int j = (tid >> 3) & 7;
    const int k = tid & 7;

    u64 r1 = 0, r2 = 0, r3 = 0;
    u64 a0 = 0, a1 = 0, a2 = 0, a3 = 0, a4 = 0, a5 = 0, a6 = 0, a7 = 0;

    const u64 c2 = C2P, c3 = C3P, c4 = C4P;

    // one Chen step body; d-values passed in registers (prefetched)
#define CHEN_STEP(dp, DI, DJ, DK)                                   \
    {                                                               \
        const ulonglong2 q0 = *(const ulonglong2*)((dp) + 0);       \
        const ulonglong2 q1 = *(const ulonglong2*)((dp) + 2);       \
        const ulonglong2 q2 = *(const ulonglong2*)((dp) + 4);       \
        const ulonglong2 q3 = *(const ulonglong2*)((dp) + 6);       \
        const u64 djk  = fmul2(DJ, DK);                             \
        const u64 dijk = fmul2(DI, djk);                            \
        const u64 u = fmul2(r2, DK);                                \
        const u64 v = fmul2(r1, djk);                               \
        u64 g = ffma2(c2, u, r3);                                   \
        FFMA2_ACC(g, c3, v);                                        \
        FFMA2_ACC(g, c4, dijk);                                     \
        FFMA2_ACC(a0, g, q0.x);                                     \
        FFMA2_ACC(a1, g, q0.y);                                     \
        FFMA2_ACC(a2, g, q1.x);                                     \
        FFMA2_ACC(a3, g, q1.y);                                     \
        FFMA2_ACC(a4, g, q2.x);                                     \
        FFMA2_ACC(a5, g, q2.y);                                     \
        FFMA2_ACC(a6, g, q3.x);                                     \
        FFMA2_ACC(a7, g, q3.y);                                     \
        FADD2_ACC(r3, u);                                           \
        FFMA2_ACC(r3, c2, v);                                       \
        FFMA2_ACC(r3, c3, dijk);                                    \
        const u64 tmp = ffma2(c2, DI, r1);                          \
        FFMA2_ACC(r2, DJ, tmp);                                     \
        FADD2_ACC(r1, DI);                                          \
    }

    {
        const u64* dptr = s_dx2;
        // prime the pipeline: d-values for t = 0
        u64 pdi = dptr[i], pdj = dptr[j], pdk = dptr[k];

        #pragma unroll 1
        for (int t = 0; t < NQ; t += 2, dptr += 2 * CH) {
            // prefetch t+1 critical-path values (always in range: NQ even)
            const u64 ndi = dptr[CH + i];
            const u64 ndj = dptr[CH + j];
            const u64 ndk = dptr[CH + k];

            CHEN_STEP(dptr, pdi, pdj, pdk);

            // prefetch t+2 (clamped on last trip; harmless redundant load)
            const u64* nx = (t + 2 < NQ) ? (dptr + 2 * CH) : dptr;
            pdi = nx[i]; pdj = nx[j]; pdk = nx[k];

            CHEN_STEP(dptr + CH, ndi, ndj, ndk);
        }
    }
#undef CHEN_STEP

    // ---- unpack lanes: A = quarter 2r, B = quarter 2r+1 ----
    float A1, B1, A2, B2, A3, B3;
    unpack2(r1, A1, B1);
    unpack2(r2, A2, B2);
    unpack2(r3, A3, B3);
    float aA[8], aB[8];
    unpack2(a0, aA[0], aB[0]); unpack2(a1, aA[1], aB[1]);
    unpack2(a2, aA[2], aB[2]); unpack2(a3, aA[3], aB[3]);
    unpack2(a4, aA[4], aB[4]); unpack2(a5, aA[5], aB[5]);
    unpack2(a6, aA[6], aB[6]); unpack2(a7, aA[7], aB[7]);

    sB3[tid] = B3;
    if (k == 0)          sB2[i * 8 + j] = B2;
    if ((tid & 63) == 0) sB1[i] = B1;
    __syncthreads();

    // ---- Chen combine lanes -> this CTA's half-signature H_r ----
    const float h1v = A1 + B1;
    const float h2v = A2 + B2 + A1 * sB1[j];
    const float h3v = A3 + B3 + A1 * sB2[j * 8 + k] + A2 * sB1[k];

    float w[8];
    {
        const float* b3row = &sB3[(j * 8 + k) * 8];
        const float* b2row = &sB2[k * 8];
        #pragma unroll
        for (int l = 0; l < 8; ++l) {
            float t4 = aA[l] + aB[l];
            t4 = fmaf(A3, sB1[l], t4);
            t4 = fmaf(A2, b2row[l], t4);
            t4 = fmaf(A1, b3row[l], t4);
            w[l] = t4;
        }
    }

    // ---- publish own half in SMEM ----
    sH[72 + tid] = h3v;
    if (k == 0)          sH[8 + (tid >> 3)] = h2v;
    if ((tid & 63) == 0) sH[i] = h1v;
    {
        float4 w0 = {w[0], w[1], w[2], w[3]};
        float4 w1 = {w[4], w[5], w[6], w[7]};
        *(float4*)(&sH4[tid * 8])     = w0;
        *(float4*)(&sH4[tid * 8 + 4]) = w1;
    }

    // barrier.cluster orders the SMEM writes before peer DSMEM reads
    cluster_sync_();

    // ---- fetch peer half via DSMEM ----
    const uint32_t peer = (uint32_t)(rank ^ 1);
    {
        const uint32_t peerH = mapa_rank(smem_u32(sH), peer);
        for (int idx = tid; idx < 146; idx += 512)           // 584 floats = 146 float4
            *(float4*)(&sP[idx * 4]) = ld_dsmem_v4(peerH + idx * 16);
    }
    // peer L4 slice for this CTA's output columns l in [4*rank, 4*rank+4)
    float4 p4;
    {
        const uint32_t peer4 = mapa_rank(smem_u32(sH4), peer);
        p4 = ld_dsmem_v4(peer4 + (tid * 8 + 4 * rank) * 4);
    }
    __syncthreads();

    // ---- Chen combine: S = H0 (x) H1 ----
    const float* Alev = (rank == 0) ? sH : sP;
    const float* Blev = (rank == 0) ? sP : sH;

    const float cA1 = Alev[i];
    const float cA2 = Alev[8 + (tid >> 3)];
    const float cA3 = Alev[72 + tid];

    const float c1v = cA1 + Blev[i];
    const float c2v = cA2 + Blev[8 + (tid >> 3)] + cA1 * Blev[j];
    const float c3v = cA3 + Blev[72 + tid] + cA1 * Blev[8 + j * 8 + k] + cA2 * Blev[k];

    // L4 combine for this CTA's 4 columns (l = 4*rank + m)
    float w4[4];
    {
        const float pv[4] = {p4.x, p4.y, p4.z, p4.w};
        #pragma unroll
        for (int m = 0; m < 4; ++m) {
            const int l = 4 * rank + m;
            const float A4v = (rank == 0) ? w[m] : pv[m];
            const float B4v = (rank == 0) ? pv[m] : w[4 + m];
            float t4 = A4v + B4v;
            t4 = fmaf(cA3, Blev[l], t4);
            t4 = fmaf(cA2, Blev[8 + k * 8 + l], t4);
            t4 = fmaf(cA1, Blev[72 + (j * 8 + k) * 8 + l], t4);
            w4[m] = t4;
        }
    }

    // publish combined levels for the log tail (CTA-local)
    sc[72 + tid] = c3v;
    if (k == 0)          sc[8 + (tid >> 3)] = c2v;
    if ((tid & 63) == 0) sc[i] = c1v;
    __syncthreads();

    // ---- closed-form log(1+x) truncated at depth 4 ----
    const float si = sc[i];
    const float sj = sc[j];
    const float sk = sc[k];
    const float s2ij  = c2v;
    const float s2jk  = sc[8 + j * 8 + k];
    const float s3ijk = c3v;

    const float cross = fmaf(si, s2jk, s2ij * sk);
    const float sss   = si * sj * sk;

    const float P = fmaf(1.0f / 3.0f, cross, -0.5f * s3ijk) - 0.25f * sss;
    const float Q = fmaf(1.0f / 3.0f, si * sj, -0.5f * s2ij);
    const float R = -0.5f * si;

    float* ob = out + (size_t)b * OUT_STRIDE;

    {
        float4 o;
        float ov[4];
        #pragma unroll
        for (int m = 0; m < 4; ++m) {
            const int l = 4 * rank + m;
            ov[m] = w4[m] + P * sc[l] + Q * sc[8 + k * 8 + l] + R * sc[72 + (j * 8 + k) * 8 + l];
        }
        o.x = ov[0]; o.y = ov[1]; o.z = ov[2]; o.w = ov[3];
        *(float4*)(&ob[OFF_L4 + tid * 8 + 4 * rank]) = o;
    }

    if (rank == 0) {
        ob[OFF_L3 + tid] = fmaf(1.0f / 3.0f, sss, fmaf(-0.5f, cross, s3ijk));
        if (k == 0)
            ob[OFF_L2 + i * 8 + j] = fmaf(-0.5f * si, sj, c2v);
        if ((tid & 63) == 0)
            ob[i] = c1v;
    }

    // keep peer SMEM alive until both CTAs are done
    cluster_sync_();
}

extern "C" void kernel_launch(void* const* d_in, const int* in_sizes, int n_in,
                              void* d_out, int out_size)
{
    const float* path = (const float*)d_in[0];
    float* out = (float*)d_out;
    logsig_fused<<<2 * BATCH, 512>>>(path, out);
}